// round 2
// baseline (speedup 1.0000x reference)
#include <cuda_runtime.h>

#define TM        8
#define NTHREADS  256
#define M_DIM     8192
#define N_DIM     8192

// ---- packed f32x2 helpers (sm_103a) ----
__device__ __forceinline__ unsigned long long pack2(float a, float b) {
    unsigned long long r;
    asm("mov.b64 %0, {%1, %2};" : "=l"(r) : "f"(a), "f"(b));
    return r;
}
__device__ __forceinline__ unsigned long long fma2(unsigned long long a,
                                                   unsigned long long b,
                                                   unsigned long long c) {
    unsigned long long d;
    asm("fma.rn.f32x2 %0, %1, %2, %3;" : "=l"(d) : "l"(a), "l"(b), "l"(c));
    return d;
}
__device__ __forceinline__ void unpack2(unsigned long long v, float& a, float& b) {
    asm("mov.b64 {%0, %1}, %2;" : "=f"(a), "=f"(b) : "l"(v));
}

// y[r][m] = sum_n code[nib(m,n)] * absmax[(m*N+n)/64] * x[r][n] + bias[m]
// qweight: one packed byte per int32. High nibble = even n, low nibble = odd n.
//
// Block: TM=8 consecutive rows of W, all of N. 8 warps split N (512 int32 each).
// Lane owns an int4 (4 packed bytes = 8 weights) per chunk; 4 chunks per lane.
// All 8 weights of a lane's int4 share one absmax block -> defer scale to 1 fma2.
__global__ void __launch_bounds__(NTHREADS, 2)
fp4_gemv_kernel(const float* __restrict__ x,
                const int*   __restrict__ qweight,
                const float* __restrict__ absmax,
                const float* __restrict__ code,
                const float* __restrict__ bias,
                float*       __restrict__ out)
{
    __shared__ float code_sh[16];          // 16 floats = 16 banks: conflict-free
    __shared__ float red[8][TM * 4];

    const int tid = threadIdx.x;
    const int w   = tid >> 5;
    const int l   = tid & 31;

    if (tid < 16) code_sh[tid] = code[tid];
    __syncthreads();

    const int m0 = blockIdx.x * TM;
    const int4* __restrict__ qw4 = (const int4*)qweight;

    unsigned long long acc01[TM], acc23[TM];   // (row r=0,1) and (r=2,3) packed
    #pragma unroll
    for (int i = 0; i < TM; ++i) { acc01[i] = 0ULL; acc23[i] = 0ULL; }

    #pragma unroll
    for (int c = 0; c < 4; ++c) {
        const int col4 = w * 128 + c * 32 + l;   // int4 index within a row [0,1024)
        const int n0   = col4 * 8;               // first weight column of this int4

        // x for the 8 columns, all 4 x-rows, interleaved as (r0,r1) / (r2,r3) pairs
        float4 r0a = __ldg((const float4*)(x + 0 * N_DIM + n0));
        float4 r0b = __ldg((const float4*)(x + 0 * N_DIM + n0 + 4));
        float4 r1a = __ldg((const float4*)(x + 1 * N_DIM + n0));
        float4 r1b = __ldg((const float4*)(x + 1 * N_DIM + n0 + 4));
        float4 r2a = __ldg((const float4*)(x + 2 * N_DIM + n0));
        float4 r2b = __ldg((const float4*)(x + 2 * N_DIM + n0 + 4));
        float4 r3a = __ldg((const float4*)(x + 3 * N_DIM + n0));
        float4 r3b = __ldg((const float4*)(x + 3 * N_DIM + n0 + 4));

        unsigned long long xp01[8], xp23[8];
        xp01[0] = pack2(r0a.x, r1a.x); xp01[1] = pack2(r0a.y, r1a.y);
        xp01[2] = pack2(r0a.z, r1a.z); xp01[3] = pack2(r0a.w, r1a.w);
        xp01[4] = pack2(r0b.x, r1b.x); xp01[5] = pack2(r0b.y, r1b.y);
        xp01[6] = pack2(r0b.z, r1b.z); xp01[7] = pack2(r0b.w, r1b.w);
        xp23[0] = pack2(r2a.x, r3a.x); xp23[1] = pack2(r2a.y, r3a.y);
        xp23[2] = pack2(r2a.z, r3a.z); xp23[3] = pack2(r2a.w, r3a.w);
        xp23[4] = pack2(r2b.x, r3b.x); xp23[5] = pack2(r2b.y, r3b.y);
        xp23[6] = pack2(r2b.z, r3b.z); xp23[7] = pack2(r2b.w, r3b.w);

        const int amcol = col4 >> 3;  // absmax block index within row

        #pragma unroll
        for (int g = 0; g < 2; ++g) {        // two groups of 4 rows: prefetch depth 4
            int4  q[4];
            float am[4];
            #pragma unroll
            for (int mi = 0; mi < 4; ++mi) {
                const int m = m0 + g * 4 + mi;
                q[mi]  = __ldg(&qw4[m * 1024 + col4]);
                am[mi] = __ldg(&absmax[m * 128 + amcol]);
            }
            #pragma unroll
            for (int mi = 0; mi < 4; ++mi) {
                unsigned long long t01 = 0ULL, t23 = 0ULL;
                const int bb[4] = { q[mi].x, q[mi].y, q[mi].z, q[mi].w };
                #pragma unroll
                for (int j = 0; j < 4; ++j) {
                    const int b = bb[j];                 // 0..255
                    const float chi = code_sh[(b >> 4) & 15];  // even column
                    const float clo = code_sh[b & 15];         // odd column
                    const unsigned long long ch2 = pack2(chi, chi);
                    const unsigned long long cl2 = pack2(clo, clo);
                    t01 = fma2(ch2, xp01[2 * j],     t01);
                    t01 = fma2(cl2, xp01[2 * j + 1], t01);
                    t23 = fma2(ch2, xp23[2 * j],     t23);
                    t23 = fma2(cl2, xp23[2 * j + 1], t23);
                }
                const unsigned long long am2 = pack2(am[mi], am[mi]);
                acc01[g * 4 + mi] = fma2(t01, am2, acc01[g * 4 + mi]);
                acc23[g * 4 + mi] = fma2(t23, am2, acc23[g * 4 + mi]);
            }
        }
    }

    // ---- reduction: warp shfl, then cross-warp via smem ----
    float vals[TM * 4];
    #pragma unroll
    for (int mi = 0; mi < TM; ++mi) {
        unpack2(acc01[mi], vals[mi * 4 + 0], vals[mi * 4 + 1]);
        unpack2(acc23[mi], vals[mi * 4 + 2], vals[mi * 4 + 3]);
    }
    #pragma unroll
    for (int i = 0; i < TM * 4; ++i) {
        float v = vals[i];
        v += __shfl_xor_sync(0xffffffffu, v, 16);
        v += __shfl_xor_sync(0xffffffffu, v, 8);
        v += __shfl_xor_sync(0xffffffffu, v, 4);
        v += __shfl_xor_sync(0xffffffffu, v, 2);
        v += __shfl_xor_sync(0xffffffffu, v, 1);
        vals[i] = v;
    }
    if (l == 0) {
        #pragma unroll
        for (int i = 0; i < TM * 4; ++i) red[w][i] = vals[i];
    }
    __syncthreads();

    if (tid < TM * 4) {
        float s = 0.0f;
        #pragma unroll
        for (int ww = 0; ww < 8; ++ww) s += red[ww][tid];
        const int mi = tid >> 2;
        const int r  = tid & 3;
        out[r * M_DIM + m0 + mi] = s + bias[m0 + mi];
    }
}

extern "C" void kernel_launch(void* const* d_in, const int* in_sizes, int n_in,
                              void* d_out, int out_size)
{
    const float* x       = (const float*)d_in[0];
    const int*   qweight = (const int*)  d_in[1];
    const float* absmax  = (const float*)d_in[2];
    const float* code    = (const float*)d_in[3];
    const float* bias    = (const float*)d_in[4];
    float*       out     = (float*)d_out;

    fp4_gemv_kernel<<<M_DIM / TM, NTHREADS>>>(x, qweight, absmax, code, bias, out);
}